// round 2
// baseline (speedup 1.0000x reference)
#include <cuda_runtime.h>
#include <cstdint>

// Problem constants
#define T_STEPS 100
#define BATCH   64
#define M_DIM   (T_STEPS * BATCH)   // 6400
#define N_DIM   1024
#define K_DIM   1024
#define THR     15.0f

// scratch: delta_us [M, N] fp32  (26 MB)
__device__ float g_delta[(size_t)M_DIM * N_DIM];

// ---------------------------------------------------------------------------
// GEMM: g_delta[m,n] = sum_k spikes[m,k] * W[n,k]  + b[n]
// FP32 SIMT, ONE accumulator per C element, strictly ascending-k FFMA chain
// (matches the canonical SGEMM accumulation order -> minimal / zero deviation
//  from the fp32 reference einsum).
// CTA tile 128x128x16, 256 threads, 8x8 per thread.
// ---------------------------------------------------------------------------

#define BM 128
#define BN 128
#define BK 16
#define SPAD 4
#define SMSTR (BM + SPAD)   // 132
#define SNSTR (BN + SPAD)   // 132

__global__ __launch_bounds__(256, 2) void gemm_kernel(
    const float* __restrict__ A,     // spikes [M, K]
    const float* __restrict__ W,     // [N, K]
    const float* __restrict__ bias)  // [N]
{
    __shared__ float As_t[BK][SMSTR];   // [k][m]
    __shared__ float Bs_t[BK][SNSTR];   // [k][n]

    const int tid = threadIdx.x;
    const int m0  = blockIdx.y * BM;
    const int n0  = blockIdx.x * BN;

    const int lane = tid & 31;
    const int warp = tid >> 5;
    const int wm   = warp & 3;          // 4 warps along M
    const int wn   = warp >> 2;         // 2 warps along N
    const int warp_m = wm * 32;
    const int warp_n = wn * 64;
    const int lm = lane >> 3;           // 0..3
    const int ln = lane & 7;            // 0..7

    const int am0 = warp_m + lm * 4;    // thread's m-frag bases
    const int am1 = am0 + 16;
    const int bn0 = warp_n + ln * 4;    // thread's n-frag bases
    const int bn1 = bn0 + 32;

    // global-load mapping: 128 rows x 16 k per tile; 2 threads per row
    const int grow = tid >> 1;          // 0..127
    const int gks  = (tid & 1) * 8;     // 0 or 8

    const float* Aptr = A + (size_t)(m0 + grow) * K_DIM + gks;
    const float* Wptr = W + (size_t)(n0 + grow) * K_DIM + gks;

    float acc[8][8];
#pragma unroll
    for (int i = 0; i < 8; i++)
#pragma unroll
        for (int j = 0; j < 8; j++) acc[i][j] = 0.0f;

    // prefetch tile 0
    float4 pa0 = *(const float4*)(Aptr);
    float4 pa1 = *(const float4*)(Aptr + 4);
    float4 pb0 = *(const float4*)(Wptr);
    float4 pb1 = *(const float4*)(Wptr + 4);

    const int NKT = K_DIM / BK;   // 64
    for (int kt = 0; kt < NKT; kt++) {
        // store prefetched tile to smem (transposed)
        As_t[gks + 0][grow] = pa0.x;
        As_t[gks + 1][grow] = pa0.y;
        As_t[gks + 2][grow] = pa0.z;
        As_t[gks + 3][grow] = pa0.w;
        As_t[gks + 4][grow] = pa1.x;
        As_t[gks + 5][grow] = pa1.y;
        As_t[gks + 6][grow] = pa1.z;
        As_t[gks + 7][grow] = pa1.w;
        Bs_t[gks + 0][grow] = pb0.x;
        Bs_t[gks + 1][grow] = pb0.y;
        Bs_t[gks + 2][grow] = pb0.z;
        Bs_t[gks + 3][grow] = pb0.w;
        Bs_t[gks + 4][grow] = pb1.x;
        Bs_t[gks + 5][grow] = pb1.y;
        Bs_t[gks + 6][grow] = pb1.z;
        Bs_t[gks + 7][grow] = pb1.w;
        __syncthreads();

        // prefetch next tile
        if (kt + 1 < NKT) {
            const float* ap = Aptr + (kt + 1) * BK;
            const float* wp = Wptr + (kt + 1) * BK;
            pa0 = *(const float4*)(ap);
            pa1 = *(const float4*)(ap + 4);
            pb0 = *(const float4*)(wp);
            pb1 = *(const float4*)(wp + 4);
        }

        // compute: k strictly ascending, one fma chain per acc element
#pragma unroll
        for (int kk = 0; kk < BK; kk++) {
            float4 a0 = *(const float4*)(&As_t[kk][am0]);
            float4 a1 = *(const float4*)(&As_t[kk][am1]);
            float4 b0 = *(const float4*)(&Bs_t[kk][bn0]);
            float4 b1 = *(const float4*)(&Bs_t[kk][bn1]);
            float av[8] = {a0.x, a0.y, a0.z, a0.w, a1.x, a1.y, a1.z, a1.w};
            float bv[8] = {b0.x, b0.y, b0.z, b0.w, b1.x, b1.y, b1.z, b1.w};
#pragma unroll
            for (int i = 0; i < 8; i++)
#pragma unroll
                for (int j = 0; j < 8; j++)
                    acc[i][j] = fmaf(av[i], bv[j], acc[i][j]);
        }
        __syncthreads();
    }

    // epilogue: single fp32 bias add (matches einsum(...) + b), float4 stores
    float4 bb0 = *(const float4*)(bias + n0 + bn0);
    float4 bb1 = *(const float4*)(bias + n0 + bn1);
    float bvz[8] = {bb0.x, bb0.y, bb0.z, bb0.w, bb1.x, bb1.y, bb1.z, bb1.w};

#pragma unroll
    for (int i = 0; i < 8; i++) {
        int m = m0 + ((i < 4) ? (am0 + i) : (am1 + i - 4));
        float4 o0, o1;
        o0.x = acc[i][0] + bvz[0];
        o0.y = acc[i][1] + bvz[1];
        o0.z = acc[i][2] + bvz[2];
        o0.w = acc[i][3] + bvz[3];
        o1.x = acc[i][4] + bvz[4];
        o1.y = acc[i][5] + bvz[5];
        o1.z = acc[i][6] + bvz[6];
        o1.w = acc[i][7] + bvz[7];
        *(float4*)(g_delta + (size_t)m * N_DIM + n0 + bn0) = o0;
        *(float4*)(g_delta + (size_t)m * N_DIM + n0 + bn1) = o1;
    }
}

// ---------------- Scan over T: per (b, out) element ------------------------
// out layout: [ ss (T*B*N) | mem_out (B*N) | hat_s (B*N) ]  all fp32
__global__ void scan_kernel(const float* __restrict__ mem_in,
                            float* __restrict__ out)
{
    const int j = blockIdx.x * blockDim.x + threadIdx.x;   // 0 .. 65535
    const int BN_ELEMS = BATCH * N_DIM;                    // 65536

    float m = mem_in[j];
    float ssum = 0.0f;

#pragma unroll 4
    for (int t = 0; t < T_STEPS; t++) {
        float du = g_delta[(size_t)t * BN_ELEMS + j];
        m += du;
        float s = (m > THR) ? 1.0f : 0.0f;
        m = fminf(fmaxf(m, 0.0f), THR);   // clip(0, thr)
        m = m - m * s;                    // reset fired neurons (exact 0)
        out[(size_t)t * BN_ELEMS + j] = s;
        ssum += s;                        // integer-valued, exact in fp32
    }

    const size_t ss_total = (size_t)T_STEPS * BN_ELEMS;    // 6,553,600
    out[ss_total + j]            = m;                      // mem_out
    out[ss_total + BN_ELEMS + j] = ssum / (float)T_STEPS;  // hat_s = ss.mean(0)
}

// ---------------------------------------------------------------------------
extern "C" void kernel_launch(void* const* d_in, const int* in_sizes, int n_in,
                              void* d_out, int out_size)
{
    const float* spikes = (const float*)d_in[0];   // [100,64,1024]
    const float* mem    = (const float*)d_in[1];   // [64,1024]
    // d_in[2] = hat_spikes: numerically dead in the forward pass
    const float* W      = (const float*)d_in[3];   // [1024,1024]
    const float* b      = (const float*)d_in[4];   // [1024]
    float* out          = (float*)d_out;

    dim3 grid(N_DIM / BN, M_DIM / BM);   // (8, 50)
    gemm_kernel<<<grid, 256>>>(spikes, W, b);

    scan_kernel<<<(BATCH * N_DIM) / 256, 256>>>(mem, out);
}

// round 4
// speedup vs baseline: 1.6995x; 1.6995x over previous
#include <cuda_runtime.h>
#include <cstdint>

// Problem constants
#define T_STEPS 100
#define BATCH   64
#define M_DIM   (T_STEPS * BATCH)   // 6400
#define N_DIM   1024
#define K_DIM   1024
#define THR     15.0f

// scratch: delta_us [M, N] fp32  (26 MB)
__device__ float g_delta[(size_t)M_DIM * N_DIM];

// ---------------------------------------------------------------------------
// GEMM: g_delta = spikes @ W^T + b   via tf32 tensor cores, EXACT products,
// and CHUNKED accumulation (KC=32) so the non-IEEE TC accumulator only ever
// integrates small-magnitude partial sums; chunk results are combined with
// IEEE fp32 adds in registers. Noise vs fp32 reference ~= ordering noise.
//   - spikes in {0,1}: exact in tf32 (no split)
//   - W = w_hi + w_lo (both tf32): products exact
// CTA tile 128x128x32, 8 warps (2 along M x 4 along N), warp tile 64x32.
// ---------------------------------------------------------------------------

#define BM 128
#define BN 128
#define BK 32
#define SPAD 4
#define SSTR (BK + SPAD)   // 36 floats per smem row (conflict-free pattern)

__device__ __forceinline__ void mma_tf32(float c[4], const uint32_t a[4], const uint32_t b[2]) {
    asm volatile(
        "mma.sync.aligned.m16n8k8.row.col.f32.tf32.tf32.f32 "
        "{%0,%1,%2,%3}, {%4,%5,%6,%7}, {%8,%9}, {%0,%1,%2,%3};\n"
        : "+f"(c[0]), "+f"(c[1]), "+f"(c[2]), "+f"(c[3])
        : "r"(a[0]), "r"(a[1]), "r"(a[2]), "r"(a[3]),
          "r"(b[0]), "r"(b[1]));
}

__device__ __forceinline__ uint32_t f32_to_tf32(float f) {
    uint32_t x;
    asm("cvt.rna.tf32.f32 %0, %1;" : "=r"(x) : "f"(f));
    return x;
}

__global__ __launch_bounds__(256, 1) void gemm_tc_kernel(
    const float* __restrict__ A,     // spikes [M, K]
    const float* __restrict__ W,     // [N, K]
    const float* __restrict__ bias)  // [N]
{
    extern __shared__ float smem[];
    float* As = smem;                        // [BM * SSTR]
    float* Bh = As + BM * SSTR;              // [BN * SSTR]
    float* Bl = Bh + BN * SSTR;              // [BN * SSTR]

    const int tid  = threadIdx.x;
    const int m0   = blockIdx.y * BM;
    const int n0   = blockIdx.x * BN;

    const int lane = tid & 31;
    const int warp = tid >> 5;
    const int wm   = warp & 1;     // 2 warps along M
    const int wn   = warp >> 1;    // 4 warps along N
    const int warp_m = wm * 64;
    const int warp_n = wn * 32;
    const int grp  = lane >> 2;    // 0..7
    const int tig  = lane & 3;     // 0..3

    // TC chunk accumulators (zeroed every k-tile) + IEEE running sums
    float acc[4][4][4];
    float sum[4][4][4];
#pragma unroll
    for (int i = 0; i < 4; i++)
#pragma unroll
        for (int j = 0; j < 4; j++)
#pragma unroll
            for (int r = 0; r < 4; r++) { acc[i][j][r] = 0.0f; sum[i][j][r] = 0.0f; }

    // global-load mapping: 256 threads, each loads 4x float4 per tile
    const int lrow = tid >> 3;        // 0..31
    const int lseg = (tid & 7) * 4;   // 0,4,...,28

    const float* Aptr = A + (size_t)(m0 + lrow) * K_DIM + lseg;
    const float* Wptr = W + (size_t)(n0 + lrow) * K_DIM + lseg;

    // prefetch tile 0
    float4 pa[4], pb[4];
#pragma unroll
    for (int r = 0; r < 4; r++) {
        pa[r] = *(const float4*)(Aptr + (size_t)r * 32 * K_DIM);
        pb[r] = *(const float4*)(Wptr + (size_t)r * 32 * K_DIM);
    }

    const int NKT = K_DIM / BK;   // 32
    for (int kt = 0; kt < NKT; kt++) {
        // store prefetched tile to smem (A raw; W split hi/lo)
#pragma unroll
        for (int r = 0; r < 4; r++) {
            int row = lrow + r * 32;
            *(float4*)(As + row * SSTR + lseg) = pa[r];
            float4 v = pb[r];
            float4 h, l;
            h.x = __uint_as_float(f32_to_tf32(v.x));
            h.y = __uint_as_float(f32_to_tf32(v.y));
            h.z = __uint_as_float(f32_to_tf32(v.z));
            h.w = __uint_as_float(f32_to_tf32(v.w));
            l.x = __uint_as_float(f32_to_tf32(v.x - h.x));   // exact residual
            l.y = __uint_as_float(f32_to_tf32(v.y - h.y));
            l.z = __uint_as_float(f32_to_tf32(v.z - h.z));
            l.w = __uint_as_float(f32_to_tf32(v.w - h.w));
            *(float4*)(Bh + row * SSTR + lseg) = h;
            *(float4*)(Bl + row * SSTR + lseg) = l;
        }
        __syncthreads();

        // prefetch next tile while computing
        if (kt + 1 < NKT) {
            const float* ap = Aptr + (kt + 1) * BK;
            const float* wp = Wptr + (kt + 1) * BK;
#pragma unroll
            for (int r = 0; r < 4; r++) {
                pa[r] = *(const float4*)(ap + (size_t)r * 32 * K_DIM);
                pb[r] = *(const float4*)(wp + (size_t)r * 32 * K_DIM);
            }
        }

#pragma unroll
        for (int kk = 0; kk < BK; kk += 8) {
            uint32_t af[4][4];
#pragma unroll
            for (int i = 0; i < 4; i++) {
                int rb = warp_m + i * 16;
                af[i][0] = __float_as_uint(As[(rb + grp    ) * SSTR + kk + tig    ]);
                af[i][1] = __float_as_uint(As[(rb + grp + 8) * SSTR + kk + tig    ]);
                af[i][2] = __float_as_uint(As[(rb + grp    ) * SSTR + kk + tig + 4]);
                af[i][3] = __float_as_uint(As[(rb + grp + 8) * SSTR + kk + tig + 4]);
            }
            uint32_t bh[4][2], bl[4][2];
#pragma unroll
            for (int j = 0; j < 4; j++) {
                int nb = warp_n + j * 8;
                bh[j][0] = __float_as_uint(Bh[(nb + grp) * SSTR + kk + tig    ]);
                bh[j][1] = __float_as_uint(Bh[(nb + grp) * SSTR + kk + tig + 4]);
                bl[j][0] = __float_as_uint(Bl[(nb + grp) * SSTR + kk + tig    ]);
                bl[j][1] = __float_as_uint(Bl[(nb + grp) * SSTR + kk + tig + 4]);
            }
#pragma unroll
            for (int i = 0; i < 4; i++)
#pragma unroll
                for (int j = 0; j < 4; j++) {
                    mma_tf32(acc[i][j], af[i], bh[j]);   // hi
                    mma_tf32(acc[i][j], af[i], bl[j]);   // lo correction
                }
        }

        // flush chunk (KC = 32): IEEE RN adds, then reset TC accumulator
#pragma unroll
        for (int i = 0; i < 4; i++)
#pragma unroll
            for (int j = 0; j < 4; j++)
#pragma unroll
                for (int r = 0; r < 4; r++) {
                    sum[i][j][r] += acc[i][j][r];
                    acc[i][j][r] = 0.0f;
                }
        __syncthreads();
    }

    // epilogue: + bias (single fp32 add, as in reference), float2 stores
#pragma unroll
    for (int i = 0; i < 4; i++) {
        int row0 = m0 + warp_m + i * 16 + grp;
#pragma unroll
        for (int j = 0; j < 4; j++) {
            int col = n0 + warp_n + j * 8 + tig * 2;
            float b0 = __ldg(bias + col);
            float b1 = __ldg(bias + col + 1);
            float2 lo = make_float2(sum[i][j][0] + b0, sum[i][j][1] + b1);
            float2 hi = make_float2(sum[i][j][2] + b0, sum[i][j][3] + b1);
            *(float2*)(g_delta + (size_t)row0       * N_DIM + col) = lo;
            *(float2*)(g_delta + (size_t)(row0 + 8) * N_DIM + col) = hi;
        }
    }
}

// ---------------- Scan over T: float4 per thread, batched loads -------------
// out layout: [ ss (T*B*N) | mem_out (B*N) | hat_s (B*N) ]  all fp32
__global__ void scan_kernel(const float* __restrict__ mem_in,
                            float* __restrict__ out)
{
    const int j4 = blockIdx.x * blockDim.x + threadIdx.x;  // 0 .. 16383
    const int j  = j4 * 4;
    const int BN_ELEMS = BATCH * N_DIM;                    // 65536

    float4 m = *(const float4*)(mem_in + j);
    float4 ssum = make_float4(0.f, 0.f, 0.f, 0.f);

    for (int t0 = 0; t0 < T_STEPS; t0 += 10) {
        float4 buf[10];
#pragma unroll
        for (int u = 0; u < 10; u++)           // MLP = 10 x 16B in flight
            buf[u] = *(const float4*)(g_delta + (size_t)(t0 + u) * BN_ELEMS + j);
#pragma unroll
        for (int u = 0; u < 10; u++) {
            float4 s;
            m.x += buf[u].x; m.y += buf[u].y; m.z += buf[u].z; m.w += buf[u].w;
            s.x = (m.x > THR) ? 1.0f : 0.0f;
            s.y = (m.y > THR) ? 1.0f : 0.0f;
            s.z = (m.z > THR) ? 1.0f : 0.0f;
            s.w = (m.w > THR) ? 1.0f : 0.0f;
            m.x = fminf(fmaxf(m.x, 0.0f), THR);
            m.y = fminf(fmaxf(m.y, 0.0f), THR);
            m.z = fminf(fmaxf(m.z, 0.0f), THR);
            m.w = fminf(fmaxf(m.w, 0.0f), THR);
            m.x -= m.x * s.x;  m.y -= m.y * s.y;
            m.z -= m.z * s.z;  m.w -= m.w * s.w;
            *(float4*)(out + (size_t)(t0 + u) * BN_ELEMS + j) = s;
            ssum.x += s.x; ssum.y += s.y; ssum.z += s.z; ssum.w += s.w;
        }
    }

    const size_t ss_total = (size_t)T_STEPS * BN_ELEMS;    // 6,553,600
    *(float4*)(out + ss_total + j) = m;                    // mem_out
    float4 hs = make_float4(ssum.x / (float)T_STEPS, ssum.y / (float)T_STEPS,
                            ssum.z / (float)T_STEPS, ssum.w / (float)T_STEPS);
    *(float4*)(out + ss_total + BN_ELEMS + j) = hs;        // hat_s
}

// ---------------------------------------------------------------------------
extern "C" void kernel_launch(void* const* d_in, const int* in_sizes, int n_in,
                              void* d_out, int out_size)
{
    const float* spikes = (const float*)d_in[0];   // [100,64,1024]
    const float* mem    = (const float*)d_in[1];   // [64,1024]
    // d_in[2] = hat_spikes: numerically dead in the forward pass
    const float* W      = (const float*)d_in[3];   // [1024,1024]
    const float* b      = (const float*)d_in[4];   // [1024]
    float* out          = (float*)d_out;

    const size_t smem_bytes = (size_t)(BM + 2 * BN) * SSTR * sizeof(float); // 55296
    cudaFuncSetAttribute(gemm_tc_kernel,
                         cudaFuncAttributeMaxDynamicSharedMemorySize,
                         (int)smem_bytes);

    dim3 grid(N_DIM / BN, M_DIM / BM);   // (8, 50)
    gemm_tc_kernel<<<grid, 256, smem_bytes>>>(spikes, W, b);

    scan_kernel<<<(BATCH * N_DIM / 4) / 256, 256>>>(mem, out);
}

// round 5
// speedup vs baseline: 1.8671x; 1.0986x over previous
#include <cuda_runtime.h>
#include <cuda_bf16.h>
#include <cstdint>

// Problem constants
#define T_STEPS 100
#define BATCH   64
#define M_DIM   (T_STEPS * BATCH)   // 6400
#define N_DIM   1024
#define K_DIM   1024
#define KP      (K_DIM / 2)         // 512 packed bf16x2 per row
#define THR     15.0f

// scratch
__device__ float    g_delta[(size_t)M_DIM * N_DIM];     // 26 MB
__device__ uint32_t g_Apk [(size_t)M_DIM * KP];         // spikes as bf16x2, 13 MB
__device__ uint32_t g_Wh  [(size_t)N_DIM * KP];         // W hi    (bf16x2), 2 MB
__device__ uint32_t g_Wm  [(size_t)N_DIM * KP];         // W mid
__device__ uint32_t g_Wl  [(size_t)N_DIM * KP];         // W lo

// ---------------------------------------------------------------------------
// Prep: exact 3-way bf16 split of W (h+m+l == w to ~2^-26), spikes -> bf16
// (exact: values are {0,1}).
// ---------------------------------------------------------------------------
__device__ __forceinline__ uint32_t pack_bf16(__nv_bfloat16 lo, __nv_bfloat16 hi) {
    return (uint32_t)__bfloat16_as_ushort(lo) | ((uint32_t)__bfloat16_as_ushort(hi) << 16);
}

__global__ void pack_a_kernel(const float* __restrict__ A) {
    int i = blockIdx.x * blockDim.x + threadIdx.x;      // pair index
    float2 v = *(const float2*)(A + (size_t)i * 2);
    g_Apk[i] = pack_bf16(__float2bfloat16_rn(v.x), __float2bfloat16_rn(v.y));
}

__global__ void pack_w_kernel(const float* __restrict__ W) {
    int i = blockIdx.x * blockDim.x + threadIdx.x;      // pair index
    float2 v = *(const float2*)(W + (size_t)i * 2);
    __nv_bfloat16 h0 = __float2bfloat16_rn(v.x);
    float r0 = v.x - __bfloat162float(h0);              // exact
    __nv_bfloat16 m0 = __float2bfloat16_rn(r0);
    __nv_bfloat16 l0 = __float2bfloat16_rn(r0 - __bfloat162float(m0));
    __nv_bfloat16 h1 = __float2bfloat16_rn(v.y);
    float r1 = v.y - __bfloat162float(h1);
    __nv_bfloat16 m1 = __float2bfloat16_rn(r1);
    __nv_bfloat16 l1 = __float2bfloat16_rn(r1 - __bfloat162float(m1));
    g_Wh[i] = pack_bf16(h0, h1);
    g_Wm[i] = pack_bf16(m0, m1);
    g_Wl[i] = pack_bf16(l0, l1);
}

// ---------------------------------------------------------------------------
// GEMM: g_delta = spikes @ W^T + b   via bf16 m16n8k16 tensor cores.
// Exact products (3-split W), chunked accumulation KC=32 (TC accumulator only
// ever sums small partials; chunks combined with IEEE fp32 adds).
// CTA 128x128x32, 8 warps (2 along M x 4 along N), warp tile 64x32.
// smem: packed bf16x2, row stride 20 u32 (conflict-free for 8-row x 4-col frag
// access pattern and for uint4 fills).
// ---------------------------------------------------------------------------
#define BM 128
#define BN 128
#define BK 32
#define BKP (BK / 2)     // 16 u32 per row per tile
#define STRU 20          // u32 stride (16 + 4 pad)

__device__ __forceinline__ void mma_bf16(float c[4], const uint32_t a[4], const uint32_t b[2]) {
    asm volatile(
        "mma.sync.aligned.m16n8k16.row.col.f32.bf16.bf16.f32 "
        "{%0,%1,%2,%3}, {%4,%5,%6,%7}, {%8,%9}, {%0,%1,%2,%3};\n"
        : "+f"(c[0]), "+f"(c[1]), "+f"(c[2]), "+f"(c[3])
        : "r"(a[0]), "r"(a[1]), "r"(a[2]), "r"(a[3]),
          "r"(b[0]), "r"(b[1]));
}

__global__ __launch_bounds__(256, 1) void gemm_tc_kernel(const float* __restrict__ bias)
{
    __shared__ uint32_t As[BM * STRU];
    __shared__ uint32_t Bs[3][BN * STRU];

    const int tid  = threadIdx.x;
    const int m0   = blockIdx.y * BM;
    const int n0   = blockIdx.x * BN;

    const int lane = tid & 31;
    const int warp = tid >> 5;
    const int wm   = warp & 1;      // 2 warps along M
    const int wn   = warp >> 1;     // 4 warps along N
    const int warp_m = wm * 64;
    const int warp_n = wn * 32;
    const int g    = lane >> 2;     // 0..7
    const int t    = lane & 3;      // 0..3

    float acc[4][4][4];             // TC chunk accumulator
    float sum[4][4][4];             // IEEE running sum
#pragma unroll
    for (int i = 0; i < 4; i++)
#pragma unroll
        for (int j = 0; j < 4; j++)
#pragma unroll
            for (int r = 0; r < 4; r++) { acc[i][j][r] = 0.0f; sum[i][j][r] = 0.0f; }

    // global-load mapping: row = tid>>1 (0..127), q = tid&1 selects 8-u32 half
    const int grow = tid >> 1;
    const int q8   = (tid & 1) * 8;

    const uint32_t* gA = g_Apk + (size_t)(m0 + grow) * KP + q8;
    const uint32_t* gH = g_Wh  + (size_t)(n0 + grow) * KP + q8;
    const uint32_t* gM = g_Wm  + (size_t)(n0 + grow) * KP + q8;
    const uint32_t* gL = g_Wl  + (size_t)(n0 + grow) * KP + q8;

    // prefetch tile 0
    uint4 pa0 = *(const uint4*)(gA);
    uint4 pa1 = *(const uint4*)(gA + 4);
    uint4 ph0 = *(const uint4*)(gH);
    uint4 ph1 = *(const uint4*)(gH + 4);
    uint4 pm0 = *(const uint4*)(gM);
    uint4 pm1 = *(const uint4*)(gM + 4);
    uint4 pl0 = *(const uint4*)(gL);
    uint4 pl1 = *(const uint4*)(gL + 4);

    const int NKT = K_DIM / BK;   // 32
    for (int kt = 0; kt < NKT; kt++) {
        {
            uint32_t* as = As + grow * STRU + q8;
            *(uint4*)(as)     = pa0;
            *(uint4*)(as + 4) = pa1;
            uint32_t* bs0 = Bs[0] + grow * STRU + q8;
            *(uint4*)(bs0)     = ph0;
            *(uint4*)(bs0 + 4) = ph1;
            uint32_t* bs1 = Bs[1] + grow * STRU + q8;
            *(uint4*)(bs1)     = pm0;
            *(uint4*)(bs1 + 4) = pm1;
            uint32_t* bs2 = Bs[2] + grow * STRU + q8;
            *(uint4*)(bs2)     = pl0;
            *(uint4*)(bs2 + 4) = pl1;
        }
        __syncthreads();

        if (kt + 1 < NKT) {
            const int off = (kt + 1) * BKP;
            pa0 = *(const uint4*)(gA + off);
            pa1 = *(const uint4*)(gA + off + 4);
            ph0 = *(const uint4*)(gH + off);
            ph1 = *(const uint4*)(gH + off + 4);
            pm0 = *(const uint4*)(gM + off);
            pm1 = *(const uint4*)(gM + off + 4);
            pl0 = *(const uint4*)(gL + off);
            pl1 = *(const uint4*)(gL + off + 4);
        }

        // two K=16 steps per tile
#pragma unroll
        for (int kkp = 0; kkp < BKP; kkp += 8) {
            uint32_t af[4][4];
#pragma unroll
            for (int i = 0; i < 4; i++) {
                int rb = (warp_m + i * 16 + g) * STRU + kkp + t;
                af[i][0] = As[rb];
                af[i][1] = As[rb + 8 * STRU];
                af[i][2] = As[rb + 4];
                af[i][3] = As[rb + 8 * STRU + 4];
            }
#pragma unroll
            for (int s = 0; s < 3; s++) {
                uint32_t bf[4][2];
#pragma unroll
                for (int j = 0; j < 4; j++) {
                    int nb = (warp_n + j * 8 + g) * STRU + kkp + t;
                    bf[j][0] = Bs[s][nb];
                    bf[j][1] = Bs[s][nb + 4];
                }
#pragma unroll
                for (int i = 0; i < 4; i++)
#pragma unroll
                    for (int j = 0; j < 4; j++)
                        mma_bf16(acc[i][j], af[i], bf[j]);
            }
        }

        // flush chunk (KC = 32): IEEE RN adds, reset TC accumulator
#pragma unroll
        for (int i = 0; i < 4; i++)
#pragma unroll
            for (int j = 0; j < 4; j++)
#pragma unroll
                for (int r = 0; r < 4; r++) {
                    sum[i][j][r] += acc[i][j][r];
                    acc[i][j][r] = 0.0f;
                }
        __syncthreads();
    }

    // epilogue: + bias (single fp32 add), float2 stores
#pragma unroll
    for (int i = 0; i < 4; i++) {
        int row0 = m0 + warp_m + i * 16 + g;
#pragma unroll
        for (int j = 0; j < 4; j++) {
            int col = n0 + warp_n + j * 8 + t * 2;
            float b0 = __ldg(bias + col);
            float b1 = __ldg(bias + col + 1);
            float2 lo = make_float2(sum[i][j][0] + b0, sum[i][j][1] + b1);
            float2 hi = make_float2(sum[i][j][2] + b0, sum[i][j][3] + b1);
            *(float2*)(g_delta + (size_t)row0       * N_DIM + col) = lo;
            *(float2*)(g_delta + (size_t)(row0 + 8) * N_DIM + col) = hi;
        }
    }
}

// ---------------- Scan over T: scalar per element, batched loads ------------
// out layout: [ ss (T*B*N) | mem_out (B*N) | hat_s (B*N) ]  all fp32
__global__ void scan_kernel(const float* __restrict__ mem_in,
                            float* __restrict__ out)
{
    const int j = blockIdx.x * blockDim.x + threadIdx.x;   // 0 .. 65535
    const int BN_ELEMS = BATCH * N_DIM;                    // 65536

    float m = mem_in[j];
    float ssum = 0.0f;

    for (int t0 = 0; t0 < T_STEPS; t0 += 10) {
        float buf[10];
#pragma unroll
        for (int u = 0; u < 10; u++)            // MLP = 10
            buf[u] = g_delta[(size_t)(t0 + u) * BN_ELEMS + j];
#pragma unroll
        for (int u = 0; u < 10; u++) {
            m += buf[u];
            float s = (m > THR) ? 1.0f : 0.0f;
            m = fminf(fmaxf(m, 0.0f), THR);     // clip(0, thr)
            m = m - m * s;                      // reset fired neurons
            out[(size_t)(t0 + u) * BN_ELEMS + j] = s;
            ssum += s;                          // integer-valued, exact
        }
    }

    const size_t ss_total = (size_t)T_STEPS * BN_ELEMS;
    out[ss_total + j]            = m;                      // mem_out
    out[ss_total + BN_ELEMS + j] = ssum / (float)T_STEPS;  // hat_s
}

// ---------------------------------------------------------------------------
extern "C" void kernel_launch(void* const* d_in, const int* in_sizes, int n_in,
                              void* d_out, int out_size)
{
    const float* spikes = (const float*)d_in[0];   // [100,64,1024]
    const float* mem    = (const float*)d_in[1];   // [64,1024]
    // d_in[2] = hat_spikes: numerically dead in the forward pass
    const float* W      = (const float*)d_in[3];   // [1024,1024]
    const float* b      = (const float*)d_in[4];   // [1024]
    float* out          = (float*)d_out;

    pack_a_kernel<<<(M_DIM * KP) / 256, 256>>>(spikes);
    pack_w_kernel<<<(N_DIM * KP) / 256, 256>>>(W);

    dim3 grid(N_DIM / BN, M_DIM / BM);   // (8, 50)
    gemm_tc_kernel<<<grid, 256>>>(b);

    scan_kernel<<<(BATCH * N_DIM) / 256, 256>>>(mem, out);
}